// round 7
// baseline (speedup 1.0000x reference)
#include <cuda_runtime.h>
#include <cuda_bf16.h>
#include <math.h>

#define NN 100000
#define NE 1000000
#define IND 64
#define HID 64
#define NC 30
#define CP 32          // padded cluster dim
#define REGC 0.01

// ---------------- scratch (static device globals; no allocation) ----------------
__device__ __align__(16) float g_deg[NN];
__device__ __align__(16) float g_dinv[NN];
__device__ __align__(16) float g_norm[NE];
__device__ __align__(16) float g_h1[NN * HID];     // x @ W1
__device__ __align__(16) float g_agg1[NN * HID];   // scatter target layer1
__device__ __align__(16) float g_h[NN * HID];      // relu output layer1
__device__ __align__(16) float g_h2[NN * CP];      // h @ W2 (padded)
__device__ __align__(16) float g_agg2[NN * CP];    // scatter target layer2
__device__ __align__(16) float g_fxp[NN * CP];     // padded softmax output
__device__ float g_S[CP];                          // sum over nodes of log1p(-fx^2)
__device__ double g_mse;                           // sum over edges (FF - w)^2
__device__ int g_is64;                             // edge_index dtype flag

// Edge-index loader: dtype decided at runtime by probe_kernel.
__device__ __forceinline__ int load_idx(const void* ei, int is64, int pos) {
    if (is64) return (int)((const long long*)ei)[pos];
    return ((const int*)ei)[pos];
}

// ---------------- kernels ----------------

// Decide whether edge_index is int64 or int32. Reads only the first 256
// entries (2 KB) — in-bounds under both interpretations. If the buffer is
// int32, an int64 interpretation combines two random ints in [0,1e5) into
// lo + hi*2^32, which lands outside [0, NN) with overwhelming probability.
__global__ void probe_kernel(const void* ei) {
    if (threadIdx.x != 0 || blockIdx.x != 0) return;
    const long long* e64 = (const long long*)ei;
    int ok64 = 1;
    for (int i = 0; i < 256; i++) {
        long long v = e64[i];
        if (v < 0 || v >= NN) { ok64 = 0; break; }
    }
    g_is64 = ok64;
}

__global__ void init_kernel() {
    int idx = blockIdx.x * blockDim.x + threadIdx.x;
    int stride = gridDim.x * blockDim.x;
    for (int i = idx; i < NN * HID; i += stride) {
        g_agg1[i] = 0.f;
        if (i < NN) g_deg[i] = 1.0f;              // self-loop weight
        if (i < NN * CP) g_agg2[i] = 0.f;
        if (i < CP) g_S[i] = 0.f;
        if (i == 0) g_mse = 0.0;
    }
}

__global__ void deg_kernel(const void* __restrict__ ei,
                           const float* __restrict__ w) {
    int e = blockIdx.x * blockDim.x + threadIdx.x;
    if (e >= NE) return;
    int is64 = g_is64;
    int dst = load_idx(ei, is64, NE + e);
    atomicAdd(&g_deg[dst], w[e]);
}

__global__ void dinv_kernel() {
    int n = blockIdx.x * blockDim.x + threadIdx.x;
    if (n >= NN) return;
    g_dinv[n] = rsqrtf(g_deg[n]);
}

__global__ void norm_kernel(const void* __restrict__ ei,
                            const float* __restrict__ w) {
    int e = blockIdx.x * blockDim.x + threadIdx.x;
    if (e >= NE) return;
    int is64 = g_is64;
    int src = load_idx(ei, is64, e);
    int dst = load_idx(ei, is64, NE + e);
    g_norm[e] = g_dinv[src] * w[e] * g_dinv[dst];
}

// h1 = x @ W1  (warp per node, W1 in smem)
__global__ void gemm1_kernel(const float* __restrict__ x,
                             const float* __restrict__ W1) {
    __shared__ float Ws[64 * 64];
    for (int i = threadIdx.x; i < 64 * 64; i += blockDim.x) Ws[i] = W1[i];
    __syncthreads();
    int gw = (blockIdx.x * blockDim.x + threadIdx.x) >> 5;
    int lane = threadIdx.x & 31;
    int nw = (gridDim.x * blockDim.x) >> 5;
    for (int n = gw; n < NN; n += nw) {
        float x0 = x[n * 64 + lane];
        float x1 = x[n * 64 + 32 + lane];
        float a0 = 0.f, a1 = 0.f;
#pragma unroll
        for (int k = 0; k < 32; k++) {
            float xk = __shfl_sync(0xffffffffu, x0, k);
            a0 += xk * Ws[k * 64 + lane];
            a1 += xk * Ws[k * 64 + 32 + lane];
        }
#pragma unroll
        for (int k = 0; k < 32; k++) {
            float xk = __shfl_sync(0xffffffffu, x1, k);
            a0 += xk * Ws[(k + 32) * 64 + lane];
            a1 += xk * Ws[(k + 32) * 64 + 32 + lane];
        }
        g_h1[n * 64 + lane] = a0;
        g_h1[n * 64 + 32 + lane] = a1;
    }
}

// scatter1: agg1[dst] += norm * h1[src] ; 16 threads per edge
__global__ void scatter1_kernel(const void* __restrict__ ei) {
    int t = blockIdx.x * blockDim.x + threadIdx.x;
    int e = t >> 4;
    if (e >= NE) return;
    int q = t & 15;
    int is64 = g_is64;
    int src = load_idx(ei, is64, e);
    int dst = load_idx(ei, is64, NE + e);
    float nm = g_norm[e];
    float4 v = *(const float4*)(g_h1 + src * 64 + q * 4);
    float* p = g_agg1 + dst * 64 + q * 4;
    atomicAdd(p + 0, nm * v.x);
    atomicAdd(p + 1, nm * v.y);
    atomicAdd(p + 2, nm * v.z);
    atomicAdd(p + 3, nm * v.w);
}

// h = relu(agg1 + h1/deg + b1)
__global__ void update1_kernel(const float* __restrict__ b1) {
    int idx = blockIdx.x * blockDim.x + threadIdx.x;   // over NN*16 float4s
    if (idx >= NN * 16) return;
    int n = idx >> 4;
    int q = idx & 15;
    float invdeg = g_dinv[n] * g_dinv[n];
    float4 a = *(const float4*)(g_agg1 + idx * 4);
    float4 h = *(const float4*)(g_h1 + idx * 4);
    float bx = __ldg(b1 + q * 4 + 0);
    float by = __ldg(b1 + q * 4 + 1);
    float bz = __ldg(b1 + q * 4 + 2);
    float bw = __ldg(b1 + q * 4 + 3);
    float4 o;
    o.x = fmaxf(a.x + h.x * invdeg + bx, 0.f);
    o.y = fmaxf(a.y + h.y * invdeg + by, 0.f);
    o.z = fmaxf(a.z + h.z * invdeg + bz, 0.f);
    o.w = fmaxf(a.w + h.w * invdeg + bw, 0.f);
    *(float4*)(g_h + idx * 4) = o;
}

// h2 = h @ W2  (padded to 32 cols; pad cols are exactly 0)
__global__ void gemm2_kernel(const float* __restrict__ W2) {
    __shared__ float Ws[64 * CP];
    for (int i = threadIdx.x; i < 64 * CP; i += blockDim.x) {
        int k = i / CP, c = i % CP;
        Ws[i] = (c < NC) ? W2[k * NC + c] : 0.f;
    }
    __syncthreads();
    int gw = (blockIdx.x * blockDim.x + threadIdx.x) >> 5;
    int lane = threadIdx.x & 31;
    int nw = (gridDim.x * blockDim.x) >> 5;
    for (int n = gw; n < NN; n += nw) {
        float r0 = g_h[n * 64 + lane];
        float r1 = g_h[n * 64 + 32 + lane];
        float acc = 0.f;
#pragma unroll
        for (int k = 0; k < 32; k++) {
            float xk = __shfl_sync(0xffffffffu, r0, k);
            acc += xk * Ws[k * CP + lane];
        }
#pragma unroll
        for (int k = 0; k < 32; k++) {
            float xk = __shfl_sync(0xffffffffu, r1, k);
            acc += xk * Ws[(k + 32) * CP + lane];
        }
        g_h2[n * CP + lane] = acc;   // pad lanes get 0 via zero weights
    }
}

// scatter2: agg2[dst] += norm * h2[src] ; 8 threads per edge (32 floats)
__global__ void scatter2_kernel(const void* __restrict__ ei) {
    int t = blockIdx.x * blockDim.x + threadIdx.x;
    int e = t >> 3;
    if (e >= NE) return;
    int q = t & 7;
    int is64 = g_is64;
    int src = load_idx(ei, is64, e);
    int dst = load_idx(ei, is64, NE + e);
    float nm = g_norm[e];
    float4 v = *(const float4*)(g_h2 + src * CP + q * 4);
    float* p = g_agg2 + dst * CP + q * 4;
    atomicAdd(p + 0, nm * v.x);
    atomicAdd(p + 1, nm * v.y);
    atomicAdd(p + 2, nm * v.z);
    atomicAdd(p + 3, nm * v.w);
}

// X2 = agg2 + h2/deg + b2 ; FX = softmax(X2) ; write FX to out + padded fxp ;
// accumulate S[c] += log1p(-fx^2)
__global__ void softmax_kernel(const float* __restrict__ b2,
                               float* __restrict__ out) {
    int gw = (blockIdx.x * blockDim.x + threadIdx.x) >> 5;
    int lane = threadIdx.x & 31;
    int nw = (gridDim.x * blockDim.x) >> 5;
    bool valid = (lane < NC);
    float bc = valid ? b2[lane] : 0.f;
    float s_local = 0.f;
    for (int n = gw; n < NN; n += nw) {
        float invdeg = g_dinv[n] * g_dinv[n];
        float xv = -INFINITY;
        if (valid)
            xv = g_agg2[n * CP + lane] + g_h2[n * CP + lane] * invdeg + bc;
        float m = xv;
#pragma unroll
        for (int o = 16; o > 0; o >>= 1)
            m = fmaxf(m, __shfl_xor_sync(0xffffffffu, m, o));
        float ev = valid ? expf(xv - m) : 0.f;
        float s = ev;
#pragma unroll
        for (int o = 16; o > 0; o >>= 1)
            s += __shfl_xor_sync(0xffffffffu, s, o);
        float fx = ev / s;
        g_fxp[n * CP + lane] = valid ? fx : 0.f;
        if (valid) {
            out[n * NC + lane] = fx;
            s_local += log1pf(-fx * fx);
        }
    }
    if (valid) atomicAdd(&g_S[lane], s_local);
}

// FF[e] = dot(FX[src], FX[dst]); mse += (FF - w)^2
__global__ void edgeloss_kernel(const void* __restrict__ ei,
                                const float* __restrict__ w) {
    __shared__ float sred[256];
    int tid = threadIdx.x;
    int idx = blockIdx.x * blockDim.x + tid;
    float local = 0.f;
    if (idx < NE) {
        int is64 = g_is64;
        int src = load_idx(ei, is64, idx);
        int dst = load_idx(ei, is64, NE + idx);
        const float4* A = (const float4*)(g_fxp) + src * 8;
        const float4* B = (const float4*)(g_fxp) + dst * 8;
        float ff = 0.f;
#pragma unroll
        for (int j = 0; j < 8; j++) {
            float4 a = A[j];
            float4 b = B[j];
            ff += a.x * b.x + a.y * b.y + a.z * b.z + a.w * b.w;
        }
        float d = ff - w[idx];
        local = d * d;
    }
    sred[tid] = local;
    __syncthreads();
    for (int o = 128; o > 0; o >>= 1) {
        if (tid < o) sred[tid] += sred[tid + o];
        __syncthreads();
    }
    if (tid == 0) atomicAdd(&g_mse, (double)sred[0]);
}

__global__ void finalize_kernel(float* __restrict__ out) {
    if (threadIdx.x != 0 || blockIdx.x != 0) return;
    double preg = 0.0;
    for (int c = 0; c < NC; c++) {
        double s = (double)g_S[c];
        preg += -log(1.0001 - exp(s));
    }
    double loss = g_mse / (double)NE + REGC * preg;
    out[NN * NC] = (float)loss;
}

// ---------------- launch ----------------
extern "C" void kernel_launch(void* const* d_in, const int* in_sizes, int n_in,
                              void* d_out, int out_size) {
    const float* x = (const float*)d_in[0];
    const void* ei = (const void*)d_in[1];
    const float* ea = (const float*)d_in[2];
    const float* W1 = (const float*)d_in[3];
    const float* b1 = (const float*)d_in[4];
    const float* W2 = (const float*)d_in[5];
    const float* b2 = (const float*)d_in[6];
    float* out = (float*)d_out;

    const int T = 256;
    probe_kernel<<<1, 32>>>(ei);
    init_kernel<<<4096, T>>>();
    deg_kernel<<<(NE + T - 1) / T, T>>>(ei, ea);
    dinv_kernel<<<(NN + T - 1) / T, T>>>();
    norm_kernel<<<(NE + T - 1) / T, T>>>(ei, ea);
    gemm1_kernel<<<592, T>>>(x, W1);
    scatter1_kernel<<<(NE * 16) / T, T>>>(ei);
    update1_kernel<<<(NN * 16 + T - 1) / T, T>>>(b1);
    gemm2_kernel<<<592, T>>>(W2);
    scatter2_kernel<<<(NE * 8) / T, T>>>(ei);
    softmax_kernel<<<592, T>>>(b2, out);
    edgeloss_kernel<<<(NE + T - 1) / T, T>>>(ei, ea);
    finalize_kernel<<<1, 1>>>(out);
}

// round 8
// speedup vs baseline: 2.1793x; 2.1793x over previous
#include <cuda_runtime.h>
#include <cuda_bf16.h>
#include <math.h>

#define NN 100000
#define NE 1000000
#define HID 64
#define NC 30
#define CP 32
#define REGC 0.01
#define NB 391        // ceil(NN/256)

// ---------------- scratch (static device globals; no allocation) ----------------
__device__ __align__(16) float g_deg[NN];
__device__ __align__(16) float g_dinv[NN];
__device__ __align__(16) float g_h1[NN * HID];     // x @ W1
__device__ __align__(16) float g_h[NN * HID];      // relu layer-1 output
__device__ __align__(16) float g_h2[NN * CP];      // h @ W2 (padded)
__device__ __align__(16) float g_fxp[NN * CP];     // padded softmax output
__device__ __align__(16) uint2 g_csr[NE];          // {src, bitcast(norm)} sorted by dst
__device__ int g_cnt[NN];
__device__ int g_rowstart[NN + 1];
__device__ int g_cursor[NN];
__device__ int g_blocksum[NB];
__device__ float g_S[CP];
__device__ double g_mse;
__device__ int g_is64;

__device__ __forceinline__ int load_idx(const void* ei, int is64, int pos) {
    if (is64) return (int)((const long long*)ei)[pos];
    return ((const int*)ei)[pos];
}

// ---------------- kernels ----------------

// Detect edge_index dtype (int32 vs int64); reads first 2KB only (safe both ways).
__global__ void probe_kernel(const void* ei) {
    if (threadIdx.x != 0 || blockIdx.x != 0) return;
    const long long* e64 = (const long long*)ei;
    int ok64 = 1;
    for (int i = 0; i < 256; i++) {
        long long v = e64[i];
        if (v < 0 || v >= NN) { ok64 = 0; break; }
    }
    g_is64 = ok64;
}

__global__ void init_kernel() {
    int n = blockIdx.x * blockDim.x + threadIdx.x;
    if (n < NN) {
        g_deg[n] = 1.0f;     // self-loop
        g_cnt[n] = 0;
    }
    if (n < CP) g_S[n] = 0.f;
    if (n == 0) g_mse = 0.0;
}

// deg (weighted) + dst histogram in one pass
__global__ void deg_hist_kernel(const void* __restrict__ ei,
                                const float* __restrict__ w) {
    int e = blockIdx.x * blockDim.x + threadIdx.x;
    if (e >= NE) return;
    int is64 = g_is64;
    int dst = load_idx(ei, is64, NE + e);
    atomicAdd(&g_deg[dst], w[e]);
    atomicAdd(&g_cnt[dst], 1);
}

__global__ void dinv_kernel() {
    int n = blockIdx.x * blockDim.x + threadIdx.x;
    if (n >= NN) return;
    g_dinv[n] = rsqrtf(g_deg[n]);
}

// ---- 3-step exclusive scan of g_cnt -> g_rowstart ----
__global__ void scan_block_kernel() {
    __shared__ int s[256];
    int n = blockIdx.x * 256 + threadIdx.x;
    s[threadIdx.x] = (n < NN) ? g_cnt[n] : 0;
    __syncthreads();
    for (int o = 128; o > 0; o >>= 1) {
        if (threadIdx.x < o) s[threadIdx.x] += s[threadIdx.x + o];
        __syncthreads();
    }
    if (threadIdx.x == 0) g_blocksum[blockIdx.x] = s[0];
}

__global__ void scan_top_kernel() {
    if (threadIdx.x != 0 || blockIdx.x != 0) return;
    int acc = 0;
    for (int b = 0; b < NB; b++) {
        int v = g_blocksum[b];
        g_blocksum[b] = acc;
        acc += v;
    }
}

__global__ void scan_final_kernel() {
    __shared__ int s[256];
    int n = blockIdx.x * 256 + threadIdx.x;
    int v = (n < NN) ? g_cnt[n] : 0;
    s[threadIdx.x] = v;
    __syncthreads();
    for (int o = 1; o < 256; o <<= 1) {
        int t = (threadIdx.x >= o) ? s[threadIdx.x - o] : 0;
        __syncthreads();
        s[threadIdx.x] += t;
        __syncthreads();
    }
    if (n < NN) {
        int excl = g_blocksum[blockIdx.x] + s[threadIdx.x] - v;
        g_rowstart[n] = excl;
        g_cursor[n] = excl;
        if (n == NN - 1) g_rowstart[NN] = excl + v;
    }
}

// bucket edges by dst: csr[pos] = {src, norm}
__global__ void fill_kernel(const void* __restrict__ ei,
                            const float* __restrict__ w) {
    int e = blockIdx.x * blockDim.x + threadIdx.x;
    if (e >= NE) return;
    int is64 = g_is64;
    int src = load_idx(ei, is64, e);
    int dst = load_idx(ei, is64, NE + e);
    float nm = g_dinv[src] * w[e] * g_dinv[dst];
    int pos = atomicAdd(&g_cursor[dst], 1);
    g_csr[pos] = make_uint2((unsigned)src, __float_as_uint(nm));
}

// h1 = x @ W1  (warp per node, W1 in smem)
__global__ void gemm1_kernel(const float* __restrict__ x,
                             const float* __restrict__ W1) {
    __shared__ float Ws[64 * 64];
    for (int i = threadIdx.x; i < 64 * 64; i += blockDim.x) Ws[i] = W1[i];
    __syncthreads();
    int gw = (blockIdx.x * blockDim.x + threadIdx.x) >> 5;
    int lane = threadIdx.x & 31;
    int nw = (gridDim.x * blockDim.x) >> 5;
    for (int n = gw; n < NN; n += nw) {
        float x0 = x[n * 64 + lane];
        float x1 = x[n * 64 + 32 + lane];
        float a0 = 0.f, a1 = 0.f;
#pragma unroll
        for (int k = 0; k < 32; k++) {
            float xk = __shfl_sync(0xffffffffu, x0, k);
            a0 += xk * Ws[k * 64 + lane];
            a1 += xk * Ws[k * 64 + 32 + lane];
        }
#pragma unroll
        for (int k = 0; k < 32; k++) {
            float xk = __shfl_sync(0xffffffffu, x1, k);
            a0 += xk * Ws[(k + 32) * 64 + lane];
            a1 += xk * Ws[(k + 32) * 64 + 32 + lane];
        }
        g_h1[n * 64 + lane] = a0;
        g_h1[n * 64 + 32 + lane] = a1;
    }
}

// CSR gather layer1 fused with self-loop + bias + relu. Warp per node.
__global__ void gather1_kernel(const float* __restrict__ b1) {
    int gw = (blockIdx.x * blockDim.x + threadIdx.x) >> 5;
    int lane = threadIdx.x & 31;
    if (gw >= NN) return;
    int n = gw;
    int beg = g_rowstart[n], end = g_rowstart[n + 1];
    float a0 = 0.f, a1 = 0.f;
    int i = beg;
    // 2-way unroll for MLP
    for (; i + 1 < end; i += 2) {
        uint2 p0 = g_csr[i];
        uint2 p1 = g_csr[i + 1];
        float nm0 = __uint_as_float(p0.y);
        float nm1 = __uint_as_float(p1.y);
        const float* r0 = g_h1 + p0.x * 64;
        const float* r1 = g_h1 + p1.x * 64;
        float v00 = r0[lane], v01 = r0[32 + lane];
        float v10 = r1[lane], v11 = r1[32 + lane];
        a0 += nm0 * v00 + nm1 * v10;
        a1 += nm0 * v01 + nm1 * v11;
    }
    if (i < end) {
        uint2 p = g_csr[i];
        float nm = __uint_as_float(p.y);
        a0 += nm * g_h1[p.x * 64 + lane];
        a1 += nm * g_h1[p.x * 64 + 32 + lane];
    }
    float invdeg = g_dinv[n] * g_dinv[n];
    a0 += g_h1[n * 64 + lane] * invdeg + b1[lane];
    a1 += g_h1[n * 64 + 32 + lane] * invdeg + b1[32 + lane];
    g_h[n * 64 + lane] = fmaxf(a0, 0.f);
    g_h[n * 64 + 32 + lane] = fmaxf(a1, 0.f);
}

// h2 = h @ W2 (padded to 32 cols; pad cols exactly 0)
__global__ void gemm2_kernel(const float* __restrict__ W2) {
    __shared__ float Ws[64 * CP];
    for (int i = threadIdx.x; i < 64 * CP; i += blockDim.x) {
        int k = i / CP, c = i % CP;
        Ws[i] = (c < NC) ? W2[k * NC + c] : 0.f;
    }
    __syncthreads();
    int gw = (blockIdx.x * blockDim.x + threadIdx.x) >> 5;
    int lane = threadIdx.x & 31;
    int nw = (gridDim.x * blockDim.x) >> 5;
    for (int n = gw; n < NN; n += nw) {
        float r0 = g_h[n * 64 + lane];
        float r1 = g_h[n * 64 + 32 + lane];
        float acc = 0.f;
#pragma unroll
        for (int k = 0; k < 32; k++) {
            float xk = __shfl_sync(0xffffffffu, r0, k);
            acc += xk * Ws[k * CP + lane];
        }
#pragma unroll
        for (int k = 0; k < 32; k++) {
            float xk = __shfl_sync(0xffffffffu, r1, k);
            acc += xk * Ws[(k + 32) * CP + lane];
        }
        g_h2[n * CP + lane] = acc;
    }
}

// CSR gather layer2 fused with softmax, FX output and S accumulation.
// Grid-stride warps (limits g_S atomic count).
__global__ void gather2_softmax_kernel(const float* __restrict__ b2,
                                       float* __restrict__ out) {
    int gw = (blockIdx.x * blockDim.x + threadIdx.x) >> 5;
    int lane = threadIdx.x & 31;
    int nw = (gridDim.x * blockDim.x) >> 5;
    bool valid = (lane < NC);
    float bc = valid ? b2[lane] : 0.f;
    float s_local = 0.f;
    for (int n = gw; n < NN; n += nw) {
        int beg = g_rowstart[n], end = g_rowstart[n + 1];
        float acc = 0.f;
        int i = beg;
        for (; i + 1 < end; i += 2) {
            uint2 p0 = g_csr[i];
            uint2 p1 = g_csr[i + 1];
            acc += __uint_as_float(p0.y) * g_h2[p0.x * CP + lane]
                 + __uint_as_float(p1.y) * g_h2[p1.x * CP + lane];
        }
        if (i < end) {
            uint2 p = g_csr[i];
            acc += __uint_as_float(p.y) * g_h2[p.x * CP + lane];
        }
        float invdeg = g_dinv[n] * g_dinv[n];
        float xv = valid ? (acc + g_h2[n * CP + lane] * invdeg + bc) : -INFINITY;
        float m = xv;
#pragma unroll
        for (int o = 16; o > 0; o >>= 1)
            m = fmaxf(m, __shfl_xor_sync(0xffffffffu, m, o));
        float ev = valid ? expf(xv - m) : 0.f;
        float s = ev;
#pragma unroll
        for (int o = 16; o > 0; o >>= 1)
            s += __shfl_xor_sync(0xffffffffu, s, o);
        float fx = ev / s;
        g_fxp[n * CP + lane] = valid ? fx : 0.f;
        if (valid) {
            out[n * NC + lane] = fx;
            s_local += log1pf(-fx * fx);
        }
    }
    if (valid) atomicAdd(&g_S[lane], s_local);
}

// FF[e] = dot(FX[src], FX[dst]); mse += (FF - w)^2
__global__ void edgeloss_kernel(const void* __restrict__ ei,
                                const float* __restrict__ w) {
    __shared__ float sred[256];
    int tid = threadIdx.x;
    int idx = blockIdx.x * blockDim.x + tid;
    float local = 0.f;
    if (idx < NE) {
        int is64 = g_is64;
        int src = load_idx(ei, is64, idx);
        int dst = load_idx(ei, is64, NE + idx);
        const float4* A = (const float4*)(g_fxp) + src * 8;
        const float4* B = (const float4*)(g_fxp) + dst * 8;
        float ff = 0.f;
#pragma unroll
        for (int j = 0; j < 8; j++) {
            float4 a = A[j];
            float4 b = B[j];
            ff += a.x * b.x + a.y * b.y + a.z * b.z + a.w * b.w;
        }
        float d = ff - w[idx];
        local = d * d;
    }
    sred[tid] = local;
    __syncthreads();
    for (int o = 128; o > 0; o >>= 1) {
        if (tid < o) sred[tid] += sred[tid + o];
        __syncthreads();
    }
    if (tid == 0) atomicAdd(&g_mse, (double)sred[0]);
}

__global__ void finalize_kernel(float* __restrict__ out) {
    if (threadIdx.x != 0 || blockIdx.x != 0) return;
    double preg = 0.0;
    for (int c = 0; c < NC; c++) {
        double s = (double)g_S[c];
        preg += -log(1.0001 - exp(s));
    }
    double loss = g_mse / (double)NE + REGC * preg;
    out[NN * NC] = (float)loss;
}

// ---------------- launch ----------------
extern "C" void kernel_launch(void* const* d_in, const int* in_sizes, int n_in,
                              void* d_out, int out_size) {
    const float* x = (const float*)d_in[0];
    const void* ei = (const void*)d_in[1];
    const float* ea = (const float*)d_in[2];
    const float* W1 = (const float*)d_in[3];
    const float* b1 = (const float*)d_in[4];
    const float* W2 = (const float*)d_in[5];
    const float* b2 = (const float*)d_in[6];
    float* out = (float*)d_out;

    const int T = 256;
    const int EB = (NE + T - 1) / T;
    probe_kernel<<<1, 32>>>(ei);
    init_kernel<<<NB, T>>>();
    deg_hist_kernel<<<EB, T>>>(ei, ea);
    dinv_kernel<<<NB, T>>>();
    scan_block_kernel<<<NB, T>>>();
    scan_top_kernel<<<1, 1>>>();
    scan_final_kernel<<<NB, T>>>();
    fill_kernel<<<EB, T>>>(ei, ea);
    gemm1_kernel<<<592, T>>>(x, W1);
    gather1_kernel<<<(NN * 32 + T - 1) / T, T>>>(b1);
    gemm2_kernel<<<592, T>>>(W2);
    gather2_softmax_kernel<<<592, T>>>(b2, out);
    edgeloss_kernel<<<EB, T>>>(ei, ea);
    finalize_kernel<<<1, 1>>>(out);
}